// round 3
// baseline (speedup 1.0000x reference)
#include <cuda_runtime.h>
#include <cstdint>

// newIF spiking neuron: T=8 timestep IF recurrence + compensation rescale.
// Purely HBM-bound: 256 MB in + 256 MB out, zero reuse. ~79us roofline floor.
// R3: 2 float4 lanes per thread (16 independent LDG.128 front-batched,
// 256B in flight per thread) to raise per-warp MLP; 256-thread blocks;
// plain loads, streaming stores.

static constexpr int T_STEPS = 8;
static constexpr int VPT     = 2;   // float4 vectors per thread

__global__ __launch_bounds__(256)
void newif_kernel(const float4* __restrict__ x,
                  const float*  __restrict__ thresh,
                  float4* __restrict__ out,
                  int n4,        // float4 lanes per timestep
                  int half_n4)   // n4 / 2 : stride between the two lanes of a thread
{
    int i = blockIdx.x * blockDim.x + threadIdx.x;
    if (i >= half_n4) return;

    const float thre      = __ldg(thresh);
    const float half_thre = 0.5f * thre;
    const float cap       = (float)T_STEPS * thre;

    // Two lane indices, each warp-coalesced: [i] and [i + half_n4].
    size_t idx0 = (size_t)i;
    size_t idx1 = (size_t)i + (size_t)half_n4;

    // Front-batch ALL loads: 16 independent LDG.128 -> deep MLP.
    float4 xv[VPT][T_STEPS];
#pragma unroll
    for (int t = 0; t < T_STEPS; ++t) {
        xv[0][t] = x[(size_t)t * (size_t)n4 + idx0];
        xv[1][t] = x[(size_t)t * (size_t)n4 + idx1];
    }

    float4 nt[VPT];
    unsigned msk[VPT][4];

#pragma unroll
    for (int v = 0; v < VPT; ++v) {
        float mem[4];
        int   cnt[4];
#pragma unroll
        for (int l = 0; l < 4; ++l) { mem[l] = half_thre; cnt[l] = 0; msk[v][l] = 0u; }

#pragma unroll
        for (int t = 0; t < T_STEPS; ++t) {
            const float* xt = reinterpret_cast<const float*>(&xv[v][t]);
#pragma unroll
            for (int l = 0; l < 4; ++l) {
                float m = mem[l] + xt[l];
                bool s = (m >= thre);          // zif(mem - thre): heaviside at 0
                if (s) { m -= thre; cnt[l]++; msk[v][l] |= (1u << t); }
                mem[l] = m;
            }
        }

        float* ntv = reinterpret_cast<float*>(&nt[v]);
#pragma unroll
        for (int l = 0; l < 4; ++l) {
            float compen = mem[l] - half_thre + (float)cnt[l] * thre;
            compen = fminf(compen, cap);
            bool cond = (compen > 0.0f) && (cnt[l] > 0);
            ntv[l] = cond ? (compen / (float)cnt[l]) : 0.0f;
        }
    }

    // Stores: 16 coalesced float4 streaming stores.
#pragma unroll
    for (int t = 0; t < T_STEPS; ++t) {
#pragma unroll
        for (int v = 0; v < VPT; ++v) {
            const float* ntv = reinterpret_cast<const float*>(&nt[v]);
            float4 o;
            o.x = (msk[v][0] >> t & 1u) ? ntv[0] : 0.0f;
            o.y = (msk[v][1] >> t & 1u) ? ntv[1] : 0.0f;
            o.z = (msk[v][2] >> t & 1u) ? ntv[2] : 0.0f;
            o.w = (msk[v][3] >> t & 1u) ? ntv[3] : 0.0f;
            size_t idx = (v == 0) ? idx0 : idx1;
            __stcs(&out[(size_t)t * (size_t)n4 + idx], o);
        }
    }
}

extern "C" void kernel_launch(void* const* d_in, const int* in_sizes, int n_in,
                              void* d_out, int out_size)
{
    const float* x      = (const float*)d_in[0];
    const float* thresh = (const float*)d_in[1];
    float* out          = (float*)d_out;

    const long long total = in_sizes[0];            // T*N elements
    const int n4      = (int)(total / T_STEPS / 4); // float4 lanes per timestep
    const int half_n4 = n4 / 2;                     // n4 is even (N = 2^23)

    const int threads = 256;
    const int blocks  = (half_n4 + threads - 1) / threads;
    newif_kernel<<<blocks, threads>>>(
        (const float4*)x, thresh, (float4*)out, n4, half_n4);
}